// round 1
// baseline (speedup 1.0000x reference)
#include <cuda_runtime.h>
#include <math.h>

#define Bsz 4
#define Nn 1024
#define Cc 512
#define Hh 8
#define DH 64
#define BH 32
#define INNER 512
#define Ff 160   // 64 (E) + 64 (S) + 32 (H)

// ---- scratch (static device allocations; no runtime alloc) ----
__device__ float g_Q[BH * Nn * DH];
__device__ float g_K[BH * Nn * DH];
__device__ float g_V[BH * Nn * DH];
__device__ float g_FQ[BH * Nn * Ff];
__device__ float g_FK[BH * Nn * Ff];
__device__ float g_QA[BH * Nn];   // |eq|^2 per query token
__device__ float g_QU[BH * Nn];   // |tanh(hq)|^2 per query token
__device__ float g_KB[BH * Nn];   // |ek|^2
__device__ float g_KV[BH * Nn];   // |tanh(hk)|^2
__device__ float g_S[(size_t)BH * Nn * Nn];  // scores -> probs (128 MB)
__device__ float g_O[Bsz * Nn * INNER];

__device__ __forceinline__ float softplusf(float x) {
    return (x > 20.f) ? x : log1pf(expf(x));
}

// ============================================================
// K1: qkv = x @ w_qkv^T, scattered into per-head Q/K/V layout
// A: x (4096 x 512, row-major), B: w_qkv (1536 x 512, row-major) -> NT GEMM
// ============================================================
__global__ __launch_bounds__(256) void k_qkv(const float* __restrict__ x,
                                             const float* __restrict__ w) {
    __shared__ float As[16][65];
    __shared__ float Bs[16][65];
    int tid = threadIdx.x;
    int ty = tid >> 4, tx = tid & 15;
    const float* Abase = x + (size_t)(blockIdx.y * 64) * Cc;
    const float* Bbase = w + (size_t)(blockIdx.x * 64) * Cc;
    float acc[4][4] = {};
    for (int k0 = 0; k0 < Cc; k0 += 16) {
#pragma unroll
        for (int i = 0; i < 4; i++) {
            int f = tid + 256 * i;
            int mm = f >> 4, kk = f & 15;
            As[kk][mm] = Abase[(size_t)mm * Cc + k0 + kk];
            Bs[kk][mm] = Bbase[(size_t)mm * Cc + k0 + kk];
        }
        __syncthreads();
#pragma unroll
        for (int kk = 0; kk < 16; kk++) {
            float a[4], b[4];
#pragma unroll
            for (int i = 0; i < 4; i++) { a[i] = As[kk][ty * 4 + i]; b[i] = Bs[kk][tx * 4 + i]; }
#pragma unroll
            for (int i = 0; i < 4; i++)
#pragma unroll
                for (int j = 0; j < 4; j++) acc[i][j] += a[i] * b[j];
        }
        __syncthreads();
    }
    int m0 = blockIdx.y * 64 + ty * 4;
    int n0 = blockIdx.x * 64 + tx * 4;
#pragma unroll
    for (int i = 0; i < 4; i++)
#pragma unroll
        for (int j = 0; j < 4; j++) {
            int m = m0 + i, jc = n0 + j;
            int b = m / Nn, n = m % Nn;
            int part = jc / INNER, r = jc % INNER;
            int h = r / DH, d = r % DH;
            float* dst = (part == 0) ? g_Q : ((part == 1) ? g_K : g_V);
            dst[((size_t)(b * Hh + h) * Nn + n) * DH + d] = acc[i][j];
        }
}

// ============================================================
// K2: per-token metric embeddings -> packed feature rows + norm scalars
// blockIdx.y: 0 = Q side, 1 = K side. 4 tokens per block.
// ============================================================
__global__ __launch_bounds__(256) void k_embed(const float* __restrict__ we, const float* __restrict__ be,
                                               const float* __restrict__ ws, const float* __restrict__ bs,
                                               const float* __restrict__ wh, const float* __restrict__ bhh) {
    __shared__ float W[Ff][65];     // [out_dim][in_dim], padded
    __shared__ float bias[Ff];
    __shared__ float qr[4][64];
    __shared__ float raw[4][Ff];
    int tid = threadIdx.x;
    for (int i = tid; i < 64 * 64; i += 256) { W[i / 64][i % 64] = we[i]; W[64 + i / 64][i % 64] = ws[i]; }
    for (int i = tid; i < 32 * 64; i += 256) W[128 + i / 64][i % 64] = wh[i];
    for (int i = tid; i < Ff; i += 256) bias[i] = (i < 64) ? be[i] : ((i < 128) ? bs[i - 64] : bhh[i - 128]);
    const float* src = (blockIdx.y == 0) ? g_Q : g_K;
    int tok0 = blockIdx.x * 4;
    for (int i = tid; i < 4 * 64; i += 256) qr[i / 64][i % 64] = src[(size_t)(tok0 + i / 64) * 64 + (i % 64)];
    __syncthreads();
    for (int i = tid; i < 4 * Ff; i += 256) {
        int tt = i / Ff, j = i % Ff;
        float s = bias[j];
#pragma unroll 8
        for (int c = 0; c < 64; c++) s += qr[tt][c] * W[j][c];
        raw[tt][j] = s;
    }
    __syncthreads();
    int w = tid >> 5, lane = tid & 31;
    if (w < 4) {
        int tt = w;
        float an = 0.f, sn = 0.f, un = 0.f;
        for (int j = lane; j < 64; j += 32) { float v = raw[tt][j]; an += v * v; }
        for (int j = 64 + lane; j < 128; j += 32) { float v = raw[tt][j]; sn += v * v; }
        {   // h part: 32 dims, one per lane; tanh in place
            int j = 128 + lane;
            float th = tanhf(raw[tt][j]);
            raw[tt][j] = th;
            un += th * th;
        }
#pragma unroll
        for (int o = 16; o; o >>= 1) {
            an += __shfl_xor_sync(0xffffffffu, an, o);
            sn += __shfl_xor_sync(0xffffffffu, sn, o);
            un += __shfl_xor_sync(0xffffffffu, un, o);
        }
        float inv = 1.f / fmaxf(sqrtf(sn), 1e-12f);
        __syncwarp();
        float* Fdst = (blockIdx.y == 0) ? g_FQ : g_FK;
        int tok = tok0 + tt;
        for (int j = lane; j < Ff; j += 32) {
            float v = raw[tt][j];
            if (j >= 64 && j < 128) v *= inv;
            Fdst[(size_t)tok * Ff + j] = v;
        }
        if (lane == 0) {
            if (blockIdx.y == 0) { g_QA[tok] = an; g_QU[tok] = un; }
            else                 { g_KB[tok] = an; g_KV[tok] = un; }
        }
    }
}

// ============================================================
// K3: combined-feature GEMM (K=160, three accumulator groups)
// + distance/score epilogue. Output: g_S scores.
// ============================================================
#define GEMM_STEP(ACC)                                                          \
    _Pragma("unroll")                                                           \
    for (int kk = 0; kk < 16; kk++) {                                           \
        float a[4], b[4];                                                       \
        _Pragma("unroll")                                                       \
        for (int i = 0; i < 4; i++) { a[i] = As[kk][ty * 4 + i]; b[i] = Bs[kk][tx * 4 + i]; } \
        _Pragma("unroll")                                                       \
        for (int i = 0; i < 4; i++)                                             \
            _Pragma("unroll")                                                   \
            for (int j = 0; j < 4; j++) ACC[i][j] += a[i] * b[j];               \
    }

__global__ __launch_bounds__(256) void k_score(const float* __restrict__ alpha,
                                               const float* __restrict__ beta,
                                               const float* __restrict__ gamma,
                                               const float* __restrict__ temp) {
    __shared__ float As[16][65];
    __shared__ float Bs[16][65];
    __shared__ float sAN[64], sUN[64], sBN[64], sVN[64];
    int bh = blockIdx.z;
    int row0 = blockIdx.y * 64, col0 = blockIdx.x * 64;
    int tid = threadIdx.x, ty = tid >> 4, tx = tid & 15;
    const float* Abase = g_FQ + ((size_t)bh * Nn + row0) * Ff;
    const float* Bbase = g_FK + ((size_t)bh * Nn + col0) * Ff;
    if (tid < 64)       { sAN[tid] = g_QA[bh * Nn + row0 + tid]; sUN[tid] = g_QU[bh * Nn + row0 + tid]; }
    else if (tid < 128) { int t = tid - 64; sBN[t] = g_KB[bh * Nn + col0 + t]; sVN[t] = g_KV[bh * Nn + col0 + t]; }
    float accE[4][4] = {}, accS[4][4] = {}, accH[4][4] = {};
    for (int kt = 0; kt < 10; ++kt) {
        int k0 = kt * 16;
#pragma unroll
        for (int i = 0; i < 4; i++) {
            int f = tid + 256 * i;
            int mm = f >> 4, kk = f & 15;
            As[kk][mm] = Abase[(size_t)mm * Ff + k0 + kk];
            Bs[kk][mm] = Bbase[(size_t)mm * Ff + k0 + kk];
        }
        __syncthreads();
        if (kt < 4)      { GEMM_STEP(accE) }
        else if (kt < 8) { GEMM_STEP(accS) }
        else             { GEMM_STEP(accH) }
        __syncthreads();
    }
    float cE = softplusf(alpha[0]);
    float cS = softplusf(beta[0]);
    float cH = softplusf(gamma[0]);
    float negInvT = -1.f / softplusf(temp[0]);
    float* Sbase = g_S + (size_t)bh * Nn * Nn;
#pragma unroll
    for (int i = 0; i < 4; i++) {
        int r = row0 + ty * 4 + i;
        float an = sAN[ty * 4 + i], un = sUN[ty * 4 + i];
#pragma unroll
        for (int j = 0; j < 4; j++) {
            int c = col0 + tx * 4 + j;
            float bn = sBN[tx * 4 + j], vn = sVN[tx * 4 + j];
            float dE = sqrtf(fmaxf(an + bn - 2.f * accE[i][j], 1e-12f));
            float sim = fminf(fmaxf(accS[i][j], -1.f + 1e-6f), 1.f - 1e-6f);
            float dS = acosf(sim);
            float dns = fmaxf(un + vn - 2.f * accH[i][j], 0.f);
            float denom = (1.f - un) * (1.f - vn);
            float arg = fmaxf(1.f + 2.f * dns / (denom + 1e-8f), 1.f + 1e-6f);
            float dHp = acoshf(arg);
            Sbase[(size_t)r * Nn + c] = negInvT * (cE * dE + cS * dS + cH * dHp);
        }
    }
}

// ============================================================
// K4: row softmax in place over g_S (one block per row of 1024)
// ============================================================
__global__ __launch_bounds__(256) void k_softmax() {
    __shared__ float red[8];
    size_t base = (size_t)blockIdx.x * Nn;
    int tid = threadIdx.x;
    float v[4];
#pragma unroll
    for (int i = 0; i < 4; i++) v[i] = g_S[base + tid + 256 * i];
    float m = fmaxf(fmaxf(v[0], v[1]), fmaxf(v[2], v[3]));
#pragma unroll
    for (int o = 16; o; o >>= 1) m = fmaxf(m, __shfl_xor_sync(0xffffffffu, m, o));
    if ((tid & 31) == 0) red[tid >> 5] = m;
    __syncthreads();
    float M = red[0];
#pragma unroll
    for (int i = 1; i < 8; i++) M = fmaxf(M, red[i]);
    float s = 0.f;
#pragma unroll
    for (int i = 0; i < 4; i++) { v[i] = __expf(v[i] - M); s += v[i]; }
#pragma unroll
    for (int o = 16; o; o >>= 1) s += __shfl_xor_sync(0xffffffffu, s, o);
    __syncthreads();
    if ((tid & 31) == 0) red[tid >> 5] = s;
    __syncthreads();
    float S = 0.f;
#pragma unroll
    for (int i = 0; i < 8; i++) S += red[i];
    float inv = 1.f / S;
#pragma unroll
    for (int i = 0; i < 4; i++) g_S[base + tid + 256 * i] = v[i] * inv;
}

// ============================================================
// K5: out = attn @ V per head; write into (b, n, h*64+d) layout
// A: P (1024 x 1024 row-major), B: V (1024 x 64 row-major, NN GEMM)
// ============================================================
__global__ __launch_bounds__(256) void k_av() {
    __shared__ float As[16][65];
    __shared__ float Bs[16][64];
    int bh = blockIdx.y;
    int row0 = blockIdx.x * 64;
    int tid = threadIdx.x, ty = tid >> 4, tx = tid & 15;
    const float* Abase = g_S + (size_t)bh * Nn * Nn + (size_t)row0 * Nn;
    const float* Vbase = g_V + (size_t)bh * Nn * DH;
    float acc[4][4] = {};
    for (int k0 = 0; k0 < Nn; k0 += 16) {
#pragma unroll
        for (int i = 0; i < 4; i++) {
            int f = tid + 256 * i;
            int mm = f >> 4, kk = f & 15;
            As[kk][mm] = Abase[(size_t)mm * Nn + k0 + kk];
        }
#pragma unroll
        for (int i = 0; i < 4; i++) {
            int f = tid + 256 * i;
            int kk = f >> 6, nn2 = f & 63;
            Bs[kk][nn2] = Vbase[(size_t)(k0 + kk) * DH + nn2];
        }
        __syncthreads();
#pragma unroll
        for (int kk = 0; kk < 16; kk++) {
            float a[4], b[4];
#pragma unroll
            for (int i = 0; i < 4; i++) { a[i] = As[kk][ty * 4 + i]; b[i] = Bs[kk][tx * 4 + i]; }
#pragma unroll
            for (int i = 0; i < 4; i++)
#pragma unroll
                for (int j = 0; j < 4; j++) acc[i][j] += a[i] * b[j];
        }
        __syncthreads();
    }
    int b = bh / Hh, h = bh % Hh;
#pragma unroll
    for (int i = 0; i < 4; i++) {
        int tok = row0 + ty * 4 + i;
#pragma unroll
        for (int j = 0; j < 4; j++) {
            int d = tx * 4 + j;
            g_O[((size_t)(b * Nn + tok)) * INNER + h * DH + d] = acc[i][j];
        }
    }
}

// ============================================================
// K6: final projection: OUT = O @ w_proj^T + b_proj (NT GEMM)
// ============================================================
__global__ __launch_bounds__(256) void k_proj(const float* __restrict__ wp,
                                              const float* __restrict__ bp,
                                              float* __restrict__ out) {
    __shared__ float As[16][65];
    __shared__ float Bs[16][65];
    int tid = threadIdx.x, ty = tid >> 4, tx = tid & 15;
    const float* Abase = g_O + (size_t)(blockIdx.y * 64) * INNER;
    const float* Bbase = wp + (size_t)(blockIdx.x * 64) * INNER;
    float acc[4][4] = {};
    for (int k0 = 0; k0 < INNER; k0 += 16) {
#pragma unroll
        for (int i = 0; i < 4; i++) {
            int f = tid + 256 * i;
            int mm = f >> 4, kk = f & 15;
            As[kk][mm] = Abase[(size_t)mm * INNER + k0 + kk];
            Bs[kk][mm] = Bbase[(size_t)mm * INNER + k0 + kk];
        }
        __syncthreads();
#pragma unroll
        for (int kk = 0; kk < 16; kk++) {
            float a[4], b[4];
#pragma unroll
            for (int i = 0; i < 4; i++) { a[i] = As[kk][ty * 4 + i]; b[i] = Bs[kk][tx * 4 + i]; }
#pragma unroll
            for (int i = 0; i < 4; i++)
#pragma unroll
                for (int j = 0; j < 4; j++) acc[i][j] += a[i] * b[j];
        }
        __syncthreads();
    }
    int m0 = blockIdx.y * 64 + ty * 4;
    int n0 = blockIdx.x * 64 + tx * 4;
#pragma unroll
    for (int i = 0; i < 4; i++)
#pragma unroll
        for (int j = 0; j < 4; j++)
            out[(size_t)(m0 + i) * Cc + n0 + j] = acc[i][j] + bp[n0 + j];
}

extern "C" void kernel_launch(void* const* d_in, const int* in_sizes, int n_in,
                              void* d_out, int out_size) {
    const float* x      = (const float*)d_in[0];
    const float* w_qkv  = (const float*)d_in[1];
    const float* w_proj = (const float*)d_in[2];
    const float* b_proj = (const float*)d_in[3];
    const float* w_e    = (const float*)d_in[4];
    const float* b_e    = (const float*)d_in[5];
    const float* w_s    = (const float*)d_in[6];
    const float* b_s    = (const float*)d_in[7];
    const float* w_h    = (const float*)d_in[8];
    const float* b_h    = (const float*)d_in[9];
    const float* alpha  = (const float*)d_in[10];
    const float* beta   = (const float*)d_in[11];
    const float* gamma  = (const float*)d_in[12];
    const float* temp   = (const float*)d_in[13];
    float* out = (float*)d_out;

    k_qkv<<<dim3(24, 64), 256>>>(x, w_qkv);
    k_embed<<<dim3(BH * Nn / 4, 2), 256>>>(w_e, b_e, w_s, b_s, w_h, b_h);
    k_score<<<dim3(16, 16, BH), 256>>>(alpha, beta, gamma, temp);
    k_softmax<<<BH * Nn, 256>>>();
    k_av<<<dim3(16, BH), 256>>>();
    k_proj<<<dim3(8, 64), 256>>>(w_proj, b_proj, out);
}